// round 15
// baseline (speedup 1.0000x reference)
#include <cuda_runtime.h>
#include <cfloat>

#define Bn 512
#define Tn 512
#define Kn 64
#define PD 8  // potentials prefetch ring depth (registers, float2 slots)

// Monotone float <-> uint order-preserving map (finite floats).
__device__ __forceinline__ unsigned fmap(float f) {
    const int i = __float_as_int(f);
    return (unsigned)(i ^ ((i >> 31) | 0x80000000));
}
__device__ __forceinline__ float funmap(unsigned u) {
    const int s = ~((int)u >> 31);
    return __int_as_float((int)(u ^ (0x80000000u | (unsigned)s)));
}

// ---------------------------------------------------------------------------
// Exact full 64-candidate scan (redo / general path), even/odd ownership.
// First max wins (ascending strict >).
// ---------------------------------------------------------------------------
__device__ __noinline__ void full_scan64(
    float a_ev, float a_od, const float2* trans2, int l,
    float& best0, float& best1, int& bi0, int& bi1)
{
    float b0 = -FLT_MAX, b1 = -FLT_MAX;
    int x0 = 0, x1 = 0;
#pragma unroll 4
    for (int i = 0; i < Kn; i++) {
        const float asel = (i & 1) ? a_od : a_ev;
        const float av = __shfl_sync(0xffffffffu, asel, i >> 1);
        const float2 tv = trans2[i * 32 + l];
        const float s0 = av + tv.x, s1 = av + tv.y;
        const bool g0 = s0 > b0; b0 = g0 ? s0 : b0; x0 = g0 ? i : x0;
        const bool g1 = s1 > b1; b1 = g1 ? s1 : b1; x1 = g1 ? i : x1;
    }
    best0 = b0; best1 = b1; bi0 = x0; bi1 = x1;
}

// Candidate fetch: alpha[i] via shuffle (uniform lane i>>1), trans column pair.
#define FETCH(i_, se_, so_)                                                 \
    {                                                                       \
        const float asel_ = ((i_) & 1) ? av_od : av_ev;                     \
        const float avv_ = __shfl_sync(0xffffffffu, asel_, (i_) >> 1);      \
        const float2 tv_ = trans2[(i_) * 32 + l];                           \
        se_ = avv_ + tv_.x;                                                 \
        so_ = avv_ + tv_.y;                                                 \
    }

// One DP step (speculative fast path). Ring slot S_ is compile-time.
// Even/odd split extraction -> 6-IMNMX merge sort -> sentinel-replace with
// c0 (duplicates are no-ops). Slots ascending; == recovery applies slot0
// last -> smallest tag wins value-ties == jnp.argmax first-max (bit-exact).
// Overflow candidates (rare) via index-aware exact loops.
#define STEP_F(T_, S_)                                                       \
    {                                                                        \
        const int t_ = (T_);                                                 \
        const float2 p_ = pr[S_];                                            \
        {                                                                    \
            const int tp_ = t_ + PD;                                         \
            const int tl_ = (tp_ <= Tn - 1) ? tp_ : (Tn - 1);                \
            const float2 n_ = pb2[tl_ * 32 + l];  /* ONE LDG.64 */           \
            pr[S_] = n_;                                                     \
            if (tp_ <= Tn - 1)  /* count each row exactly once */            \
                cnt += (int)(n_.x != 0.0f) + (int)(n_.y != 0.0f);            \
        }                                                                    \
        const float av_ev = a.x, av_od = a.y;                                \
        /* extraction: two parallel 2-deep 32-bit chains, sentinel 255 */    \
        const int e0 = m_ev ? 2 * (__ffs((int)m_ev) - 1) : 255;              \
        const unsigned me2 = m_ev & (m_ev - 1);                              \
        const int e1 = me2 ? 2 * (__ffs((int)me2) - 1) : 255;                \
        unsigned mrev = me2 & (me2 - 1);                                     \
        const int o0 = m_od ? 2 * (__ffs((int)m_od) - 1) + 1 : 255;          \
        const unsigned mo2 = m_od & (m_od - 1);                              \
        const int o1 = mo2 ? 2 * (__ffs((int)mo2) - 1) + 1 : 255;            \
        unsigned mrod = mo2 & (mo2 - 1);                                     \
        /* merge-sort 4 (each list ascending) */                             \
        const int c0 = min(e0, o0);                                          \
        const int x1_ = max(e0, o0), x2_ = min(e1, o1);                      \
        int c1 = min(x1_, x2_), c2 = max(x1_, x2_);                          \
        int c3 = max(e1, o1);                                                \
        /* sentinel-replace with c0 (always valid: >=1 candidate exists) */  \
        c1 = (c1 > 63) ? c0 : c1;                                            \
        c2 = (c2 > 63) ? c0 : c2;                                            \
        c3 = (c3 > 63) ? c0 : c3;                                            \
        float s0e, s0o, s1e, s1o, s2e, s2o, s3e, s3o;                        \
        FETCH(c0, s0e, s0o); FETCH(c1, s1e, s1o);                            \
        FETCH(c2, s2e, s2o); FETCH(c3, s3e, s3o);                            \
        /* FMNMX tree: best is bitwise one of the candidates */              \
        float best0 = fmaxf(fmaxf(s0e, s1e), fmaxf(s2e, s3e));               \
        float best1 = fmaxf(fmaxf(s0o, s1o), fmaxf(s2o, s3o));               \
        /* recovery: descending slots, slot0 (smallest tag) applied last */  \
        int bi0 = c3, bi1 = c3;                                              \
        bi0 = (s2e == best0) ? c2 : bi0;  bi1 = (s2o == best1) ? c2 : bi1;   \
        bi0 = (s1e == best0) ? c1 : bi0;  bi1 = (s1o == best1) ? c1 : bi1;   \
        bi0 = (s0e == best0) ? c0 : bi0;  bi1 = (s0o == best1) ? c0 : bi1;   \
        if (mrev | mrod) { /* rare: exact, index-aware tie-break */          \
            while (mrev) {                                                   \
                const int i_ = 2 * (__ffs((int)mrev) - 1);                   \
                mrev &= mrev - 1;                                            \
                float se_, so_;                                              \
                FETCH(i_, se_, so_);                                         \
                { const bool g = (se_ > best0) ||                            \
                                 (se_ == best0 && i_ < bi0);                 \
                  best0 = g ? se_ : best0;  bi0 = g ? i_ : bi0; }            \
                { const bool g = (so_ > best1) ||                            \
                                 (so_ == best1 && i_ < bi1);                 \
                  best1 = g ? so_ : best1;  bi1 = g ? i_ : bi1; }            \
            }                                                                \
            while (mrod) {                                                   \
                const int i_ = 2 * (__ffs((int)mrod) - 1) + 1;               \
                mrod &= mrod - 1;                                            \
                float se_, so_;                                              \
                FETCH(i_, se_, so_);                                         \
                { const bool g = (se_ > best0) ||                            \
                                 (se_ == best0 && i_ < bi0);                 \
                  best0 = g ? se_ : best0;  bi0 = g ? i_ : bi0; }            \
                { const bool g = (so_ > best1) ||                            \
                                 (so_ == best1 && i_ < bi1);                 \
                  best1 = g ? so_ : best1;  bi1 = g ? i_ : bi1; }            \
            }                                                                \
        }                                                                    \
        a.x = p_.x + best0;                                                  \
        a.y = p_.y + best1;                                                  \
        /* packed backpointer store: one STS.16 per lane */                  \
        bp16[(t_ - 1) * 32 + l] =                                            \
            (unsigned short)((unsigned)bi0 | ((unsigned)bi1 << 8));          \
        /* EXACT threshold for the next step (proven R8 form) */             \
        const unsigned am_ = fmap(a.x), ah_ = fmap(a.y);                     \
        const unsigned wm_ =                                                 \
            __reduce_max_sync(0xffffffffu, am_ > ah_ ? am_ : ah_);           \
        const float thr_ = funmap(wm_) - rTp;                                \
        m_ev = __ballot_sync(0xffffffffu, a.x >= thr_);                      \
        m_od = __ballot_sync(0xffffffffu, a.y >= thr_);                      \
    }

// ---------------------------------------------------------------------------
// Single-warp Viterbi: even/odd ownership, exact-threshold pruning, fused
// seq-len count with speculative fast path + exact redo.
// ---------------------------------------------------------------------------
__global__ __launch_bounds__(32) void viterbi_kernel(
    const float* __restrict__ pots,   // [B, T, K]
    const float* __restrict__ trans,  // [K, K]
    float* __restrict__ out)          // [B, T] float32
{
    extern __shared__ float2 trans2[];              // [64][32]: (T[i][2l], T[i][2l+1])
    __shared__ unsigned short bp16[(Tn - 1) * 32];  // packed (bi_ev | bi_od<<8)
    __shared__ unsigned char tags[Tn];
    __shared__ __align__(8) float alpha_f[Kn];

    const int b = blockIdx.x;
    const int l = threadIdx.x;  // lane; owns tags 2l and 2l+1

    // ---- Prologue: stage transitions (even/odd float2) + padded range ----
    const float4* tr4 = (const float4*)trans;
    float tmin = FLT_MAX, tmax = -FLT_MAX;
#pragma unroll
    for (int q = 0; q < 32; q++) {
        const int idx = q * 32 + l;
        const float4 v = tr4[idx];
        tmin = fminf(tmin, fminf(fminf(v.x, v.y), fminf(v.z, v.w)));
        tmax = fmaxf(tmax, fmaxf(fmaxf(v.x, v.y), fmaxf(v.z, v.w)));
        const int i = idx >> 4;            // from-tag
        const int jb = (idx & 15) * 4;     // first to-tag (even)
        trans2[i * 32 + (jb >> 1)]     = make_float2(v.x, v.y);
        trans2[i * 32 + (jb >> 1) + 1] = make_float2(v.z, v.w);
    }
    const unsigned rmn = __reduce_min_sync(0xffffffffu, fmap(tmin));
    const unsigned rmx = __reduce_max_sync(0xffffffffu, fmap(tmax));
    const float r = funmap(rmx) - funmap(rmn);
    const float rTp = r + fabsf(r) * 1e-5f + 0.01f;  // pad only ADDS candidates
    __syncwarp();

    const float2* pb2 = (const float2*)(pots + (size_t)b * Tn * Kn);
    int cnt = 0;  // per-lane nonzero count (each row touched exactly once)

    float2 a = pb2[l];  // alpha0 (tags 2l, 2l+1)
    cnt += (int)(a.x != 0.0f) + (int)(a.y != 0.0f);  // row 0

    // ---------------- SPECULATIVE FAST PATH (assume sl == Tn) --------------
    unsigned m_ev, m_od;
    {
        const unsigned am = fmap(a.x), ah = fmap(a.y);
        const unsigned wm = __reduce_max_sync(0xffffffffu, am > ah ? am : ah);
        const float thr = funmap(wm) - rTp;
        m_ev = __ballot_sync(0xffffffffu, a.x >= thr);
        m_od = __ballot_sync(0xffffffffu, a.y >= thr);
    }
    float2 pr[PD];
#pragma unroll
    for (int d = 1; d <= PD; d++) {  // rows 1..PD counted here
        const float2 n = pb2[d * 32 + l];
        pr[d & (PD - 1)] = n;
        cnt += (int)(n.x != 0.0f) + (int)(n.y != 0.0f);
    }
    {
        int t = 1;
#pragma unroll 1
        for (int tb = 0; tb < 63; tb++) {
            STEP_F(t + 0, 1); STEP_F(t + 1, 2); STEP_F(t + 2, 3); STEP_F(t + 3, 4);
            STEP_F(t + 4, 5); STEP_F(t + 5, 6); STEP_F(t + 6, 7); STEP_F(t + 7, 0);
            t += 8;
        }
        STEP_F(t + 0, 1); STEP_F(t + 1, 2); STEP_F(t + 2, 3); STEP_F(t + 3, 4);
        STEP_F(t + 4, 5); STEP_F(t + 5, 6); STEP_F(t + 6, 7);
    }

    // ---- Verify speculation: exact seq_len from the fused count ----
    const int total = __reduce_add_sync(0xffffffffu, cnt);
    const int sl = total >> 6;  // floor(mean over K=64), exact

    if (sl < Tn) {
        // -------- RARE EXACT REDO: general path with mask semantics --------
        a = pb2[l];
#pragma unroll 1
        for (int t = 1; t < Tn; t++) {
            if (t < sl) {
                float best0, best1; int bi0, bi1;
                full_scan64(a.x, a.y, trans2, l, best0, best1, bi0, bi1);
                const float2 p = pb2[t * 32 + l];
                a.x = p.x + best0;
                a.y = p.y + best1;
                bp16[(t - 1) * 32 + l] =
                    (unsigned short)((unsigned)bi0 | ((unsigned)bi1 << 8));
            } else {
                bp16[(t - 1) * 32 + l] =
                    (unsigned short)((unsigned)(2 * l) | ((unsigned)(2 * l + 1) << 8));
            }
        }
    }

    // Final alpha -> smem for the backtrace scan (vectorized write)
    ((float2*)alpha_f)[l] = a;
    __syncwarp();

    // Backtrace (smem pointer-chase) by lane 0. First max wins.
    if (l == 0) {
        float bv = alpha_f[0];
        int bt = 0;
#pragma unroll 1
        for (int i = 1; i < Kn; i++) {
            const float v = alpha_f[i];
            if (v > bv) { bv = v; bt = i; }
        }
        int tg = bt;
        tags[Tn - 1] = (unsigned char)tg;
#pragma unroll 1
        for (int tt = Tn - 2; tt >= 0; tt--) {
            const unsigned v = bp16[tt * 32 + (tg >> 1)];
            tg = (int)((v >> ((tg & 1) * 8)) & 0xffu);
            tags[tt] = (unsigned char)tg;
        }
    }
    __syncwarp();

    // Coalesced float32 output write (16 per lane).
    float* ob = out + (size_t)b * Tn;
#pragma unroll
    for (int tt = l; tt < Tn; tt += 32) ob[tt] = (float)tags[tt];
}

// ---------------------------------------------------------------------------
extern "C" void kernel_launch(void* const* d_in, const int* in_sizes, int n_in,
                              void* d_out, int out_size) {
    const float* inputs = nullptr;
    const float* transitions = nullptr;
    for (int i = 0; i < n_in; i++) {
        if (in_sizes[i] == Kn * Kn) transitions = (const float*)d_in[i];
        else if (in_sizes[i] == Bn * Tn * Kn) inputs = (const float*)d_in[i];
    }
    if (!inputs) inputs = (const float*)d_in[0];
    if (!transitions) transitions = (const float*)d_in[1];

    float* out = (float*)d_out;

    // Static (~33.5 KB) + 16 KB dynamic -> opt in (host config, capture-safe).
    cudaFuncSetAttribute(viterbi_kernel,
                         cudaFuncAttributeMaxDynamicSharedMemorySize,
                         Kn * 32 * (int)sizeof(float2));

    viterbi_kernel<<<Bn, 32, Kn * 32 * sizeof(float2)>>>(inputs, transitions, out);
}

// round 16
// speedup vs baseline: 1.3312x; 1.3312x over previous
#include <cuda_runtime.h>
#include <cfloat>

#define Bn 512
#define Tn 512
#define Kn 64
#define PD 8  // potentials prefetch ring depth (registers)

// Monotone float <-> uint order-preserving map (finite floats).
__device__ __forceinline__ unsigned fmap(float f) {
    const int i = __float_as_int(f);
    return (unsigned)(i ^ ((i >> 31) | 0x80000000));
}
__device__ __forceinline__ float funmap(unsigned u) {
    const int s = ~((int)u >> 31);
    return __int_as_float((int)(u ^ (0x80000000u | (unsigned)s)));
}

// ---------------------------------------------------------------------------
// Exact full 64-candidate scan (redo / general path). First max wins.
// ---------------------------------------------------------------------------
__device__ __noinline__ void full_scan64(
    float a_lo, float a_hi, const float2* trans2, int l,
    float& best0, float& best1, int& bi0, int& bi1)
{
    float b0 = -FLT_MAX, b1 = -FLT_MAX;
    int x0 = 0, x1 = 0;
#pragma unroll 4
    for (int i = 0; i < Kn; i++) {
        const float asel = (i < 32) ? a_lo : a_hi;
        const float av = __shfl_sync(0xffffffffu, asel, i & 31);
        const float2 tv = trans2[i * 32 + l];
        const float s0 = av + tv.x, s1 = av + tv.y;
        const bool g0 = s0 > b0; b0 = g0 ? s0 : b0; x0 = g0 ? i : x0;
        const bool g1 = s1 > b1; b1 = g1 ? s1 : b1; x1 = g1 ? i : x1;
    }
    best0 = b0; best1 = b1; bi0 = x0; bi1 = x1;
}

// Candidate fetch: alpha[i] via shuffle (uniform lane), trans column pair.
#define FETCH(i_, s0_, s1_)                                                 \
    {                                                                       \
        const float asel_ = ((i_) < 32) ? a_lo : a_hi;                      \
        const float av_ = __shfl_sync(0xffffffffu, asel_, (i_) & 31);       \
        const float2 tv_ = trans2[(i_) * 32 + l];                           \
        s0_ = av_ + tv_.x;                                                  \
        s1_ = av_ + tv_.y;                                                  \
    }

// One DP step (speculative fast path). Ring slot S_ is compile-time.
// Split-half extraction, now 3-DEEP per half (parallel chains), 6 slots
// processed branchlessly (sentinel-dup pads are no-ops). Slots globally
// ascending (lo half < hi half); == recovery applies slot0 last -> smallest
// tag wins value-ties == jnp.argmax first-max (bit-exact). Fallback fires
// only for >=4 candidates in one half (rare) via index-aware exact loops.
#define STEP_F(T_, S_)                                                       \
    {                                                                        \
        const int t_ = (T_);                                                 \
        const float p_lo = plo[S_];                                          \
        const float p_hi = phi[S_];                                          \
        {                                                                    \
            const int tp_ = t_ + PD;                                         \
            const int tl_ = (tp_ <= Tn - 1) ? tp_ : (Tn - 1);                \
            const float nl_ = pb[tl_ * Kn + l];                              \
            const float nh_ = pb[tl_ * Kn + 32 + l];                         \
            plo[S_] = nl_;                                                   \
            phi[S_] = nh_;                                                   \
            if (tp_ <= Tn - 1)  /* count each row exactly once */            \
                cnt += (int)(nl_ != 0.0f) + (int)(nh_ != 0.0f);              \
        }                                                                    \
        /* two PARALLEL 3-deep 32-bit extraction chains */                   \
        int e0 = __ffs((int)m_lo) - 1;                                       \
        const unsigned me2 = m_lo & (m_lo - 1);                              \
        int e1 = me2 ? (__ffs((int)me2) - 1) : e0;                           \
        const unsigned me3 = me2 & (me2 - 1);                                \
        int e2 = me3 ? (__ffs((int)me3) - 1) : e1;                           \
        unsigned mrest_lo = me3 & (me3 - 1);                                 \
        int h0 = m_hi ? (__ffs((int)m_hi) + 31) : -1;                        \
        const unsigned mh2 = m_hi & (m_hi - 1);                              \
        int h1 = mh2 ? (__ffs((int)mh2) + 31) : h0;                          \
        const unsigned mh3 = mh2 & (mh2 - 1);                                \
        int h2 = mh3 ? (__ffs((int)mh3) + 31) : h1;                          \
        unsigned mrest_hi = mh3 & (mh3 - 1);                                 \
        if (!m_lo) { e0 = h0; e1 = h0; e2 = h0; }  /* pad: dup valid tag */  \
        if (!m_hi) { h0 = e0; h1 = e0; h2 = e0; }  /* (both-empty imposs.) */\
        float s0e, s0o, s1e, s1o, s2e, s2o, s3e, s3o, s4e, s4o, s5e, s5o;    \
        FETCH(e0, s0e, s0o); FETCH(e1, s1e, s1o); FETCH(e2, s2e, s2o);       \
        FETCH(h0, s3e, s3o); FETCH(h1, s4e, s4o); FETCH(h2, s5e, s5o);       \
        /* FMNMX tree over 6: best is bitwise one of the candidates */       \
        float best0 = fmaxf(fmaxf(fmaxf(s0e, s1e), fmaxf(s2e, s3e)),         \
                            fmaxf(s4e, s5e));                                \
        float best1 = fmaxf(fmaxf(fmaxf(s0o, s1o), fmaxf(s2o, s3o)),         \
                            fmaxf(s4o, s5o));                                \
        /* recovery: descending slots, slot0 (smallest tag) applied last */  \
        int bi0 = h2, bi1 = h2;                                              \
        bi0 = (s4e == best0) ? h1 : bi0;  bi1 = (s4o == best1) ? h1 : bi1;   \
        bi0 = (s3e == best0) ? h0 : bi0;  bi1 = (s3o == best1) ? h0 : bi1;   \
        bi0 = (s2e == best0) ? e2 : bi0;  bi1 = (s2o == best1) ? e2 : bi1;   \
        bi0 = (s1e == best0) ? e1 : bi0;  bi1 = (s1o == best1) ? e1 : bi1;   \
        bi0 = (s0e == best0) ? e0 : bi0;  bi1 = (s0o == best1) ? e0 : bi1;   \
        if (mrest_lo | mrest_hi) { /* rare: exact, index-aware tie-break */  \
            while (mrest_lo) {                                               \
                const int i_ = __ffs((int)mrest_lo) - 1;                     \
                mrest_lo &= mrest_lo - 1;                                    \
                float se_, so_;                                              \
                FETCH(i_, se_, so_);                                         \
                { const bool g = (se_ > best0) ||                            \
                                 (se_ == best0 && i_ < bi0);                 \
                  best0 = g ? se_ : best0;  bi0 = g ? i_ : bi0; }            \
                { const bool g = (so_ > best1) ||                            \
                                 (so_ == best1 && i_ < bi1);                 \
                  best1 = g ? so_ : best1;  bi1 = g ? i_ : bi1; }            \
            }                                                                \
            while (mrest_hi) {                                               \
                const int i_ = __ffs((int)mrest_hi) + 31;                    \
                mrest_hi &= mrest_hi - 1;                                    \
                float se_, so_;                                              \
                FETCH(i_, se_, so_);                                         \
                { const bool g = (se_ > best0) ||                            \
                                 (se_ == best0 && i_ < bi0);                 \
                  best0 = g ? se_ : best0;  bi0 = g ? i_ : bi0; }            \
                { const bool g = (so_ > best1) ||                            \
                                 (so_ == best1 && i_ < bi1);                 \
                  best1 = g ? so_ : best1;  bi1 = g ? i_ : bi1; }            \
            }                                                                \
        }                                                                    \
        a_lo = p_lo + best0;                                                 \
        a_hi = p_hi + best1;                                                 \
        bp[(t_ - 1) * Kn + l] = (unsigned char)bi0;                          \
        bp[(t_ - 1) * Kn + 32 + l] = (unsigned char)bi1;                     \
        /* EXACT threshold for the next step (proven R8 form) */             \
        const unsigned am_ = fmap(a_lo), ah_ = fmap(a_hi);                   \
        const unsigned wm_ =                                                 \
            __reduce_max_sync(0xffffffffu, am_ > ah_ ? am_ : ah_);           \
        const float thr_ = funmap(wm_) - rTp;                                \
        m_lo = __ballot_sync(0xffffffffu, a_lo >= thr_);                     \
        m_hi = __ballot_sync(0xffffffffu, a_hi >= thr_);                     \
    }

// ---------------------------------------------------------------------------
// Single-warp Viterbi with exact-threshold pruning + fused seq-len count.
// ---------------------------------------------------------------------------
__global__ __launch_bounds__(32) void viterbi_kernel(
    const float* __restrict__ pots,   // [B, T, K]
    const float* __restrict__ trans,  // [K, K]
    float* __restrict__ out)          // [B, T] float32
{
    extern __shared__ float2 trans2[];            // [64][32]: (T[i][l], T[i][l+32])
    __shared__ unsigned char bp[(Tn - 1) * Kn];   // 32704 B
    __shared__ unsigned char tags[Tn];
    __shared__ float alpha_f[Kn];

    const int b = blockIdx.x;
    const int l = threadIdx.x;  // lane; owns to-tags l and l+32

    // ---- Prologue: stage transitions (float2-packed) + padded range ----
    const float4* tr4 = (const float4*)trans;
    float tmin = FLT_MAX, tmax = -FLT_MAX;
#pragma unroll
    for (int q = 0; q < 32; q++) {
        const int idx = q * 32 + l;
        const float4 v = tr4[idx];
        tmin = fminf(tmin, fminf(fminf(v.x, v.y), fminf(v.z, v.w)));
        tmax = fmaxf(tmax, fmaxf(fmaxf(v.x, v.y), fmaxf(v.z, v.w)));
        const int base = idx * 4;
        const int i = base >> 6;
        const int c = base & 63;
        if (c < 32) {
            trans2[i * 32 + c + 0].x = v.x;
            trans2[i * 32 + c + 1].x = v.y;
            trans2[i * 32 + c + 2].x = v.z;
            trans2[i * 32 + c + 3].x = v.w;
        } else {
            const int cc = c - 32;
            trans2[i * 32 + cc + 0].y = v.x;
            trans2[i * 32 + cc + 1].y = v.y;
            trans2[i * 32 + cc + 2].y = v.z;
            trans2[i * 32 + cc + 3].y = v.w;
        }
    }
    const unsigned rmn = __reduce_min_sync(0xffffffffu, fmap(tmin));
    const unsigned rmx = __reduce_max_sync(0xffffffffu, fmap(tmax));
    const float r = funmap(rmx) - funmap(rmn);
    const float rTp = r + fabsf(r) * 1e-5f + 0.01f;  // pad only ADDS candidates
    __syncwarp();

    const float* pb = pots + (size_t)b * Tn * Kn;
    int cnt = 0;  // per-lane nonzero count (rows each touched exactly once)

    float a_lo = pb[l];
    float a_hi = pb[32 + l];
    cnt += (int)(a_lo != 0.0f) + (int)(a_hi != 0.0f);  // row 0

    // ---------------- SPECULATIVE FAST PATH (assume sl == Tn) --------------
    unsigned m_lo, m_hi;
    {
        const unsigned am = fmap(a_lo), ah = fmap(a_hi);
        const unsigned wm = __reduce_max_sync(0xffffffffu, am > ah ? am : ah);
        const float thr = funmap(wm) - rTp;
        m_lo = __ballot_sync(0xffffffffu, a_lo >= thr);
        m_hi = __ballot_sync(0xffffffffu, a_hi >= thr);
    }
    float plo[PD], phi[PD];
#pragma unroll
    for (int d = 1; d <= PD; d++) {  // rows 1..PD counted here
        const float nl = pb[d * Kn + l];
        const float nh = pb[d * Kn + 32 + l];
        plo[d & (PD - 1)] = nl;
        phi[d & (PD - 1)] = nh;
        cnt += (int)(nl != 0.0f) + (int)(nh != 0.0f);
    }
    {
        int t = 1;
#pragma unroll 1
        for (int tb = 0; tb < 63; tb++) {
            STEP_F(t + 0, 1); STEP_F(t + 1, 2); STEP_F(t + 2, 3); STEP_F(t + 3, 4);
            STEP_F(t + 4, 5); STEP_F(t + 5, 6); STEP_F(t + 6, 7); STEP_F(t + 7, 0);
            t += 8;
        }
        STEP_F(t + 0, 1); STEP_F(t + 1, 2); STEP_F(t + 2, 3); STEP_F(t + 3, 4);
        STEP_F(t + 4, 5); STEP_F(t + 5, 6); STEP_F(t + 6, 7);
    }

    // ---- Verify speculation: exact seq_len from the fused count ----
    const int total = __reduce_add_sync(0xffffffffu, cnt);
    const int sl = total >> 6;  // floor(mean over K=64), exact

    if (sl < Tn) {
        // -------- RARE EXACT REDO: general path with mask semantics --------
        a_lo = pb[l];
        a_hi = pb[32 + l];
#pragma unroll 1
        for (int t = 1; t < Tn; t++) {
            if (t < sl) {
                float best0, best1; int bi0, bi1;
                full_scan64(a_lo, a_hi, trans2, l, best0, best1, bi0, bi1);
                a_lo = pb[t * Kn + l] + best0;
                a_hi = pb[t * Kn + 32 + l] + best1;
                bp[(t - 1) * Kn + l] = (unsigned char)bi0;
                bp[(t - 1) * Kn + 32 + l] = (unsigned char)bi1;
            } else {
                bp[(t - 1) * Kn + l] = (unsigned char)l;
                bp[(t - 1) * Kn + 32 + l] = (unsigned char)(32 + l);
            }
        }
    }

    // Final alpha -> smem for the backtrace scan
    alpha_f[l] = a_lo;
    alpha_f[32 + l] = a_hi;
    __syncwarp();

    // Backtrace (smem pointer-chase) by lane 0. First max wins.
    if (l == 0) {
        float bv = alpha_f[0];
        int bt = 0;
#pragma unroll 1
        for (int i = 1; i < Kn; i++) {
            const float v = alpha_f[i];
            if (v > bv) { bv = v; bt = i; }
        }
        int tg = bt;
        tags[Tn - 1] = (unsigned char)tg;
#pragma unroll 1
        for (int tt = Tn - 2; tt >= 0; tt--) {
            tg = bp[tt * Kn + tg];
            tags[tt] = (unsigned char)tg;
        }
    }
    __syncwarp();

    // Coalesced float32 output write (16 per lane).
    float* ob = out + (size_t)b * Tn;
#pragma unroll
    for (int tt = l; tt < Tn; tt += 32) ob[tt] = (float)tags[tt];
}

// ---------------------------------------------------------------------------
extern "C" void kernel_launch(void* const* d_in, const int* in_sizes, int n_in,
                              void* d_out, int out_size) {
    const float* inputs = nullptr;
    const float* transitions = nullptr;
    for (int i = 0; i < n_in; i++) {
        if (in_sizes[i] == Kn * Kn) transitions = (const float*)d_in[i];
        else if (in_sizes[i] == Bn * Tn * Kn) inputs = (const float*)d_in[i];
    }
    if (!inputs) inputs = (const float*)d_in[0];
    if (!transitions) transitions = (const float*)d_in[1];

    float* out = (float*)d_out;

    // Static (~33.5 KB) + 16 KB dynamic -> opt in (host config, capture-safe).
    cudaFuncSetAttribute(viterbi_kernel,
                         cudaFuncAttributeMaxDynamicSharedMemorySize,
                         Kn * 32 * (int)sizeof(float2));

    viterbi_kernel<<<Bn, 32, Kn * 32 * sizeof(float2)>>>(inputs, transitions, out);
}